// round 2
// baseline (speedup 1.0000x reference)
#include <cuda_runtime.h>
#include <math.h>
#include <float.h>

#define BB 2
#define SS 2048
#define DD 1024
#define HH 16
#define HD 64
#define TK 32
#define AW 8
#define SCALE 0.125f

// Scratch (static __device__, no allocations)
__device__ float g_qbuf[(size_t)BB*SS*2*DD];
__device__ float g_kbuf[(size_t)BB*SS*2*DD];
__device__ float g_vbuf[(size_t)BB*SS*DD];
__device__ float g_q1[(size_t)BB*HH*SS*HD];
__device__ float g_q2[(size_t)BB*HH*SS*HD];
__device__ float g_k1[(size_t)BB*HH*SS*HD];
__device__ float g_k2[(size_t)BB*HH*SS*HD];
__device__ float g_o2[(size_t)BB*SS*DD];
__device__ float g_lam[HH];

// ---------------------------------------------------------------------------
// lambda[h] = 0.2 + exp(dot(lq1,lk1)) - exp(dot(lq2,lk2))
// ---------------------------------------------------------------------------
__global__ void lambda_kernel(const float* __restrict__ lq1, const float* __restrict__ lk1,
                              const float* __restrict__ lq2, const float* __restrict__ lk2) {
    int h = threadIdx.x;
    if (h < HH) {
        float s1 = 0.f, s2 = 0.f;
        for (int d = 0; d < HD; d++) {
            s1 += lq1[h*HD+d] * lk1[h*HD+d];
            s2 += lq2[h*HD+d] * lk2[h*HD+d];
        }
        g_lam[h] = 0.2f + expf(s1) - expf(s2);
    }
}

// ---------------------------------------------------------------------------
// C[m,n] = sum_k A[m,k] * W[n,k] + bias[n]
// A: [M,K] row-major, W: [N,K] row-major. 128x128x16 tiles, 8x8 microtile.
// M,N multiples of 128; K multiple of 16.
// ---------------------------------------------------------------------------
__global__ __launch_bounds__(256) void gemm_nt_bias(
    const float* __restrict__ A, const float* __restrict__ W,
    const float* __restrict__ bias, float* __restrict__ C,
    int M, int N, int K)
{
    __shared__ float As[16][128];
    __shared__ float Bs[16][128];
    int t = threadIdx.x;
    int tx = t & 15, ty = t >> 4;
    int m0 = blockIdx.y << 7, n0 = blockIdx.x << 7;
    int lr = t & 127;
    int lk = (t >> 7) << 3;
    const float* Ap = A + (size_t)(m0 + lr) * K + lk;
    const float* Wp = W + (size_t)(n0 + lr) * K + lk;
    float acc[8][8];
    #pragma unroll
    for (int i = 0; i < 8; i++)
        #pragma unroll
        for (int j = 0; j < 8; j++) acc[i][j] = 0.f;

    for (int k0 = 0; k0 < K; k0 += 16) {
        float4 a0 = *(const float4*)(Ap + k0);
        float4 a1 = *(const float4*)(Ap + k0 + 4);
        float4 w0 = *(const float4*)(Wp + k0);
        float4 w1 = *(const float4*)(Wp + k0 + 4);
        __syncthreads();
        As[lk+0][lr] = a0.x; As[lk+1][lr] = a0.y; As[lk+2][lr] = a0.z; As[lk+3][lr] = a0.w;
        As[lk+4][lr] = a1.x; As[lk+5][lr] = a1.y; As[lk+6][lr] = a1.z; As[lk+7][lr] = a1.w;
        Bs[lk+0][lr] = w0.x; Bs[lk+1][lr] = w0.y; Bs[lk+2][lr] = w0.z; Bs[lk+3][lr] = w0.w;
        Bs[lk+4][lr] = w1.x; Bs[lk+5][lr] = w1.y; Bs[lk+6][lr] = w1.z; Bs[lk+7][lr] = w1.w;
        __syncthreads();
        #pragma unroll
        for (int kk = 0; kk < 16; kk++) {
            float4 ar0 = *(const float4*)&As[kk][ty*8];
            float4 ar1 = *(const float4*)&As[kk][ty*8+4];
            float4 br0 = *(const float4*)&Bs[kk][tx*8];
            float4 br1 = *(const float4*)&Bs[kk][tx*8+4];
            float ar[8] = {ar0.x, ar0.y, ar0.z, ar0.w, ar1.x, ar1.y, ar1.z, ar1.w};
            float br[8] = {br0.x, br0.y, br0.z, br0.w, br1.x, br1.y, br1.z, br1.w};
            #pragma unroll
            for (int i = 0; i < 8; i++)
                #pragma unroll
                for (int j = 0; j < 8; j++)
                    acc[i][j] += ar[i] * br[j];
        }
    }
    float bb[8];
    #pragma unroll
    for (int j = 0; j < 8; j++) bb[j] = bias[n0 + tx*8 + j];
    #pragma unroll
    for (int i = 0; i < 8; i++) {
        size_t off = (size_t)(m0 + ty*8 + i) * N + n0 + tx*8;
        float4 r0 = make_float4(acc[i][0]+bb[0], acc[i][1]+bb[1], acc[i][2]+bb[2], acc[i][3]+bb[3]);
        float4 r1 = make_float4(acc[i][4]+bb[4], acc[i][5]+bb[5], acc[i][6]+bb[6], acc[i][7]+bb[7]);
        *(float4*)(C + off) = r0;
        *(float4*)(C + off + 4) = r1;
    }
}

// ---------------------------------------------------------------------------
// RoPE + transpose: src [B,S,H,2*HD] -> o1,o2 [B,H,S,HD]
// ---------------------------------------------------------------------------
__global__ __launch_bounds__(256) void rope_kernel(const float* __restrict__ src,
                                                   float* __restrict__ o1, float* __restrict__ o2) {
    int idx = blockIdx.x * blockDim.x + threadIdx.x;
    int d = idx & (HD-1);
    int s = (idx >> 6) & (SS-1);
    int h = (idx >> 17) & (HH-1);
    int b = idx >> 21;
    size_t base = ((size_t)(b*SS + s))*(2*DD) + (size_t)h*(2*HD);
    int dr = (d < 32) ? d : d - 32;
    // inv_freq = 10000^(-dr/32) = 2^(-dr * log2(10000)/32)
    float inv = exp2f(-(float)dr * 0.4152410118609203f);
    float ang = (float)s * inv;
    float sn, cs;
    sincosf(ang, &sn, &cs);
    float v1, v2;
    if (d < 32) {
        v1 = src[base + d]      * cs - src[base + d + 32]      * sn;
        v2 = src[base + 64 + d] * cs - src[base + 64 + d + 32] * sn;
    } else {
        v1 = src[base + d - 32]      * sn + src[base + d]      * cs;
        v2 = src[base + 64 + d - 32] * sn + src[base + 64 + d] * cs;
    }
    size_t o = ((size_t)((b*HH + h)*SS + s))*HD + d;
    o1[o] = v1;
    o2[o] = v2;
}

// ---------------------------------------------------------------------------
// Dual-stream flash attention + diff combine + per-head RMSNorm.
// One warp per query row; 8 rows per block; 32-key tiles.
// q1/q2/k1/k2: [B,H,S,HD]; v: [B,S,H,HD] (=[B,S,D]); out: [B,S,D]
// ---------------------------------------------------------------------------
__global__ __launch_bounds__(256) void attn_kernel(
    const float* __restrict__ q1, const float* __restrict__ q2,
    const float* __restrict__ k1, const float* __restrict__ k2,
    const float* __restrict__ v, const float* __restrict__ hw,
    float* __restrict__ out)
{
    __shared__ float k1T[HD][TK+1];
    __shared__ float k2T[HD][TK+1];
    __shared__ float vs[TK][HD];
    __shared__ float q1s[AW][HD];
    __shared__ float q2s[AW][HD];
    int b = blockIdx.z, h = blockIdx.y;
    int base = blockIdx.x * AW;
    int t = threadIdx.x;
    int w = t >> 5, lane = t & 31;
    int row = base + w;
    size_t bh = (size_t)b * HH + h;
    const float* q1p = q1 + (bh * SS + row) * HD;
    const float* q2p = q2 + (bh * SS + row) * HD;
    q1s[w][lane]     = q1p[lane];
    q1s[w][lane+32]  = q1p[lane+32];
    q2s[w][lane]     = q2p[lane];
    q2s[w][lane+32]  = q2p[lane+32];
    float lam = g_lam[h];
    const float* k1b = k1 + bh * SS * HD;
    const float* k2b = k2 + bh * SS * HD;
    const float* vb  = v + (size_t)b * SS * DD + h * HD;

    float m1 = -FLT_MAX, m2 = -FLT_MAX, z1 = 0.f, z2 = 0.f;
    float a10 = 0.f, a11 = 0.f, a20 = 0.f, a21 = 0.f;
    int ntiles = (base + AW - 1) / TK + 1;
    int lj = t >> 3;          // key row 0..31 for cooperative loads
    int ld = (t & 7) << 3;    // dim offset 0..56

    for (int tt = 0; tt < ntiles; tt++) {
        int kbase = tt * TK;
        __syncthreads();
        {
            const float4* p1 = (const float4*)(k1b + (size_t)(kbase + lj)*HD + ld);
            float4 x0 = p1[0], x1 = p1[1];
            k1T[ld+0][lj]=x0.x; k1T[ld+1][lj]=x0.y; k1T[ld+2][lj]=x0.z; k1T[ld+3][lj]=x0.w;
            k1T[ld+4][lj]=x1.x; k1T[ld+5][lj]=x1.y; k1T[ld+6][lj]=x1.z; k1T[ld+7][lj]=x1.w;
            const float4* p2 = (const float4*)(k2b + (size_t)(kbase + lj)*HD + ld);
            float4 y0 = p2[0], y1 = p2[1];
            k2T[ld+0][lj]=y0.x; k2T[ld+1][lj]=y0.y; k2T[ld+2][lj]=y0.z; k2T[ld+3][lj]=y0.w;
            k2T[ld+4][lj]=y1.x; k2T[ld+5][lj]=y1.y; k2T[ld+6][lj]=y1.z; k2T[ld+7][lj]=y1.w;
            const float4* pv = (const float4*)(vb + (size_t)(kbase + lj)*DD + ld);
            float4 v0 = pv[0], v1 = pv[1];
            *(float4*)&vs[lj][ld]   = v0;
            *(float4*)&vs[lj][ld+4] = v1;
        }
        __syncthreads();
        if (row >= kbase) {
            int nvalid = row - kbase + 1;
            if (nvalid > TK) nvalid = TK;
            float s1 = -FLT_MAX, s2 = -FLT_MAX;
            if (lane < nvalid) {
                float d1 = 0.f, d2 = 0.f;
                #pragma unroll
                for (int d = 0; d < HD; d++) {
                    d1 += q1s[w][d] * k1T[d][lane];
                    d2 += q2s[w][d] * k2T[d][lane];
                }
                s1 = d1 * SCALE; s2 = d2 * SCALE;
            }
            float tm1 = s1, tm2 = s2;
            #pragma unroll
            for (int o = 16; o > 0; o >>= 1) {
                tm1 = fmaxf(tm1, __shfl_xor_sync(0xffffffffu, tm1, o));
                tm2 = fmaxf(tm2, __shfl_xor_sync(0xffffffffu, tm2, o));
            }
            float nm1 = fmaxf(m1, tm1), nm2 = fmaxf(m2, tm2);
            float c1 = __expf(m1 - nm1), c2 = __expf(m2 - nm2);
            float p1v = (lane < nvalid) ? __expf(s1 - nm1) : 0.f;
            float p2v = (lane < nvalid) ? __expf(s2 - nm2) : 0.f;
            float ps1 = p1v, ps2 = p2v;
            #pragma unroll
            for (int o = 16; o > 0; o >>= 1) {
                ps1 += __shfl_xor_sync(0xffffffffu, ps1, o);
                ps2 += __shfl_xor_sync(0xffffffffu, ps2, o);
            }
            z1 = z1 * c1 + ps1;
            z2 = z2 * c2 + ps2;
            a10 *= c1; a11 *= c1; a20 *= c2; a21 *= c2;
            m1 = nm1; m2 = nm2;
            for (int j = 0; j < nvalid; j++) {
                float pj1 = __shfl_sync(0xffffffffu, p1v, j);
                float pj2 = __shfl_sync(0xffffffffu, p2v, j);
                a10 += pj1 * vs[j][lane];
                a11 += pj1 * vs[j][lane+32];
                a20 += pj2 * vs[j][lane];
                a21 += pj2 * vs[j][lane+32];
            }
        }
    }
    // combine + RMSNorm + head scale + (1 - lambda_init)
    float o0 = a10 / z1 - lam * (a20 / z2);
    float o1 = a11 / z1 - lam * (a21 / z2);
    float ssum = o0*o0 + o1*o1;
    #pragma unroll
    for (int o = 16; o > 0; o >>= 1)
        ssum += __shfl_xor_sync(0xffffffffu, ssum, o);
    float r = rsqrtf(ssum * (1.f/64.f) + 1e-6f);
    float sc = 0.8f * r;
    o0 *= sc * hw[h*HD + lane];
    o1 *= sc * hw[h*HD + lane + 32];
    size_t oo = ((size_t)(b*SS + row)) * DD + h*HD;
    out[oo + lane]      = o0;
    out[oo + lane + 32] = o1;
}

// ---------------------------------------------------------------------------
extern "C" void kernel_launch(void* const* d_in, const int* in_sizes, int n_in,
                              void* d_out, int out_size) {
    const float* x   = (const float*)d_in[0];
    const float* Wq  = (const float*)d_in[1];
    const float* bq  = (const float*)d_in[2];
    const float* Wk  = (const float*)d_in[3];
    const float* bk  = (const float*)d_in[4];
    const float* Wv  = (const float*)d_in[5];
    const float* bv  = (const float*)d_in[6];
    const float* Wo  = (const float*)d_in[7];
    const float* bo  = (const float*)d_in[8];
    const float* hw  = (const float*)d_in[9];
    const float* lq1 = (const float*)d_in[10];
    const float* lk1 = (const float*)d_in[11];
    const float* lq2 = (const float*)d_in[12];
    const float* lk2 = (const float*)d_in[13];

    float *qbuf, *kbuf, *vbuf, *q1, *q2, *k1, *k2, *o2;
    cudaGetSymbolAddress((void**)&qbuf, g_qbuf);
    cudaGetSymbolAddress((void**)&kbuf, g_kbuf);
    cudaGetSymbolAddress((void**)&vbuf, g_vbuf);
    cudaGetSymbolAddress((void**)&q1,   g_q1);
    cudaGetSymbolAddress((void**)&q2,   g_q2);
    cudaGetSymbolAddress((void**)&k1,   g_k1);
    cudaGetSymbolAddress((void**)&k2,   g_k2);
    cudaGetSymbolAddress((void**)&o2,   g_o2);

    lambda_kernel<<<1, 32>>>(lq1, lk1, lq2, lk2);
    gemm_nt_bias<<<dim3(16, 32), 256>>>(x, Wq, bq, qbuf, BB*SS, 2*DD, DD);
    gemm_nt_bias<<<dim3(16, 32), 256>>>(x, Wk, bk, kbuf, BB*SS, 2*DD, DD);
    gemm_nt_bias<<<dim3(8, 32), 256>>>(x, Wv, bv, vbuf, BB*SS, DD, DD);
    int nrope = BB*HH*SS*HD;
    rope_kernel<<<nrope/256, 256>>>(qbuf, q1, q2);
    rope_kernel<<<nrope/256, 256>>>(kbuf, k1, k2);
    attn_kernel<<<dim3(SS/AW, HH, BB), 256>>>(q1, q2, k1, k2, vbuf, hw, (float*)o2);
    gemm_nt_bias<<<dim3(8, 32), 256>>>(o2, Wo, bo, (float*)d_out, BB*SS, DD, DD);
}

// round 11
// speedup vs baseline: 1.6113x; 1.6113x over previous
#include <cuda_runtime.h>
#include <math.h>
#include <float.h>

#define BB 2
#define SS 2048
#define DD 1024
#define HH 16
#define HD 64
#define TK 32
#define SCALE 0.125f

// Scratch (static __device__, no allocations)
__device__ float g_qbuf[(size_t)BB*SS*2*DD];
__device__ float g_kbuf[(size_t)BB*SS*2*DD];
__device__ float g_vbuf[(size_t)BB*SS*DD];
__device__ float g_q1[(size_t)BB*HH*SS*HD];
__device__ float g_q2[(size_t)BB*HH*SS*HD];
__device__ float g_k1[(size_t)BB*HH*SS*HD];
__device__ float g_k2[(size_t)BB*HH*SS*HD];
__device__ float g_o2[(size_t)BB*SS*DD];
__device__ float g_lam[HH];

// ---------------------------------------------------------------------------
__global__ void lambda_kernel(const float* __restrict__ lq1, const float* __restrict__ lk1,
                              const float* __restrict__ lq2, const float* __restrict__ lk2) {
    int h = threadIdx.x;
    if (h < HH) {
        float s1 = 0.f, s2 = 0.f;
        for (int d = 0; d < HD; d++) {
            s1 += lq1[h*HD+d] * lk1[h*HD+d];
            s2 += lq2[h*HD+d] * lk2[h*HD+d];
        }
        g_lam[h] = 0.2f + expf(s1) - expf(s2);
    }
}

// ---------------------------------------------------------------------------
// Shared GEMM body: C[m,n] = sum_k A[m,k]*W[n,k] + bias[n]. 128x128x16 tile.
// ---------------------------------------------------------------------------
__device__ __forceinline__ void gemm_body(
    const float* __restrict__ A, const float* __restrict__ W,
    const float* __restrict__ bias, float* __restrict__ C,
    int m0, int n0, int N, int K)
{
    __shared__ float As[16][128];
    __shared__ float Bs[16][128];
    int t = threadIdx.x;
    int tx = t & 15, ty = t >> 4;
    int lr = t & 127;
    int lk = (t >> 7) << 3;
    const float* Ap = A + (size_t)(m0 + lr) * K + lk;
    const float* Wp = W + (size_t)(n0 + lr) * K + lk;
    float acc[8][8];
    #pragma unroll
    for (int i = 0; i < 8; i++)
        #pragma unroll
        for (int j = 0; j < 8; j++) acc[i][j] = 0.f;

    for (int k0 = 0; k0 < K; k0 += 16) {
        float4 a0 = *(const float4*)(Ap + k0);
        float4 a1 = *(const float4*)(Ap + k0 + 4);
        float4 w0 = *(const float4*)(Wp + k0);
        float4 w1 = *(const float4*)(Wp + k0 + 4);
        __syncthreads();
        As[lk+0][lr] = a0.x; As[lk+1][lr] = a0.y; As[lk+2][lr] = a0.z; As[lk+3][lr] = a0.w;
        As[lk+4][lr] = a1.x; As[lk+5][lr] = a1.y; As[lk+6][lr] = a1.z; As[lk+7][lr] = a1.w;
        Bs[lk+0][lr] = w0.x; Bs[lk+1][lr] = w0.y; Bs[lk+2][lr] = w0.z; Bs[lk+3][lr] = w0.w;
        Bs[lk+4][lr] = w1.x; Bs[lk+5][lr] = w1.y; Bs[lk+6][lr] = w1.z; Bs[lk+7][lr] = w1.w;
        __syncthreads();
        #pragma unroll
        for (int kk = 0; kk < 16; kk++) {
            float4 ar0 = *(const float4*)&As[kk][ty*8];
            float4 ar1 = *(const float4*)&As[kk][ty*8+4];
            float4 br0 = *(const float4*)&Bs[kk][tx*8];
            float4 br1 = *(const float4*)&Bs[kk][tx*8+4];
            float ar[8] = {ar0.x, ar0.y, ar0.z, ar0.w, ar1.x, ar1.y, ar1.z, ar1.w};
            float br[8] = {br0.x, br0.y, br0.z, br0.w, br1.x, br1.y, br1.z, br1.w};
            #pragma unroll
            for (int i = 0; i < 8; i++)
                #pragma unroll
                for (int j = 0; j < 8; j++)
                    acc[i][j] += ar[i] * br[j];
        }
    }
    float bb[8];
    #pragma unroll
    for (int j = 0; j < 8; j++) bb[j] = bias[n0 + tx*8 + j];
    #pragma unroll
    for (int i = 0; i < 8; i++) {
        size_t off = (size_t)(m0 + ty*8 + i) * N + n0 + tx*8;
        float4 r0 = make_float4(acc[i][0]+bb[0], acc[i][1]+bb[1], acc[i][2]+bb[2], acc[i][3]+bb[3]);
        float4 r1 = make_float4(acc[i][4]+bb[4], acc[i][5]+bb[5], acc[i][6]+bb[6], acc[i][7]+bb[7]);
        *(float4*)(C + off) = r0;
        *(float4*)(C + off + 4) = r1;
    }
}

__global__ __launch_bounds__(256) void gemm_nt_bias(
    const float* __restrict__ A, const float* __restrict__ W,
    const float* __restrict__ bias, float* __restrict__ C,
    int M, int N, int K)
{
    gemm_body(A, W, bias, C, blockIdx.y << 7, blockIdx.x << 7, N, K);
}

// Fused QKV projection: 40 n-tiles (16 Q, 16 K, 8 V) x 32 m-tiles
__global__ __launch_bounds__(256) void gemm_qkv(
    const float* __restrict__ x,
    const float* __restrict__ Wq, const float* __restrict__ bq,
    const float* __restrict__ Wk, const float* __restrict__ bk,
    const float* __restrict__ Wv, const float* __restrict__ bv,
    float* __restrict__ qo, float* __restrict__ ko, float* __restrict__ vo)
{
    int nb = blockIdx.x;
    const float *W, *bias; float* C; int N, n0;
    if (nb < 16)      { W = Wq; bias = bq; C = qo; N = 2048; n0 = nb * 128; }
    else if (nb < 32) { W = Wk; bias = bk; C = ko; N = 2048; n0 = (nb-16) * 128; }
    else              { W = Wv; bias = bv; C = vo; N = 1024; n0 = (nb-32) * 128; }
    gemm_body(x, W, bias, C, blockIdx.y << 7, n0, N, DD);
}

// ---------------------------------------------------------------------------
// RoPE + transpose: src [B,S,H,2*HD] -> o1,o2 [B,H,S,HD]
// ---------------------------------------------------------------------------
__global__ __launch_bounds__(256) void rope_kernel(const float* __restrict__ src,
                                                   float* __restrict__ o1, float* __restrict__ o2) {
    int idx = blockIdx.x * blockDim.x + threadIdx.x;
    int d = idx & (HD-1);
    int s = (idx >> 6) & (SS-1);
    int h = (idx >> 17) & (HH-1);
    int b = idx >> 21;
    size_t base = ((size_t)(b*SS + s))*(2*DD) + (size_t)h*(2*HD);
    int dr = (d < 32) ? d : d - 32;
    float inv = exp2f(-(float)dr * 0.4152410118609203f);
    float ang = (float)s * inv;
    float sn, cs;
    sincosf(ang, &sn, &cs);
    float v1, v2;
    if (d < 32) {
        v1 = src[base + d]      * cs - src[base + d + 32]      * sn;
        v2 = src[base + 64 + d] * cs - src[base + 64 + d + 32] * sn;
    } else {
        v1 = src[base + d - 32]      * sn + src[base + d]      * cs;
        v2 = src[base + 64 + d - 32] * sn + src[base + 64 + d] * cs;
    }
    size_t o = ((size_t)((b*HH + h)*SS + s))*HD + d;
    o1[o] = v1;
    o2[o] = v2;
}

// ---------------------------------------------------------------------------
// Dual-stream flash attention, register-tiled.
// Block: 256 threads = 8 warps, 64 query rows (8/warp). Key tiles of 32.
// Dynamic smem layout (floats):
//   k1T [64][33]   @ 0
//   k2T [64][33]   @ 2112
//   vs  [32][64]   @ 4224
//   q1s [64][64]   @ 6272
//   q2s [64][64]   @ 10368
//   ps1 [64][36]   @ 14464
//   ps2 [64][36]   @ 16772
//   cs  [64][2]    @ 19076
// total 19204 floats = 76816 B
// ---------------------------------------------------------------------------
#define SM_K1T 0
#define SM_K2T 2112
#define SM_VS  4224
#define SM_Q1S 6272
#define SM_Q2S 10368
#define SM_PS1 14464
#define SM_PS2 16772
#define SM_CS  19076
#define ATTN_SMEM_BYTES (19204*4)

__global__ __launch_bounds__(256) void attn_kernel(
    const float* __restrict__ q1, const float* __restrict__ q2,
    const float* __restrict__ k1, const float* __restrict__ k2,
    const float* __restrict__ v, const float* __restrict__ hw,
    float* __restrict__ out)
{
    extern __shared__ float sm[];
    float* k1T = sm + SM_K1T;
    float* k2T = sm + SM_K2T;
    float* vs  = sm + SM_VS;
    float* q1s = sm + SM_Q1S;
    float* q2s = sm + SM_Q2S;
    float* ps1 = sm + SM_PS1;
    float* ps2 = sm + SM_PS2;
    float* cs  = sm + SM_CS;

    int b = blockIdx.z, h = blockIdx.y;
    int base = blockIdx.x * 64;
    int t = threadIdx.x, w = t >> 5, lane = t & 31;
    size_t bh = (size_t)b * HH + h;

    // stage Q block [64 rows][64 d] both streams
    {
        int row = t >> 2, ds = (t & 3) * 16;
        const float4* p1 = (const float4*)(q1 + (bh*SS + base + row)*HD + ds);
        const float4* p2 = (const float4*)(q2 + (bh*SS + base + row)*HD + ds);
        float4* d1 = (float4*)(q1s + row*64 + ds);
        float4* d2 = (float4*)(q2s + row*64 + ds);
        d1[0]=p1[0]; d1[1]=p1[1]; d1[2]=p1[2]; d1[3]=p1[3];
        d2[0]=p2[0]; d2[1]=p2[1]; d2[2]=p2[2]; d2[3]=p2[3];
    }

    // softmax-owner state (lane<16): pair = (row r = lane&7, stream = lane>>3)
    float mst = -FLT_MAX, zst = 0.f;
    int pr = lane & 7, pstr = (lane >> 3) & 1;

    // PV accumulators: lane owns d = lane and lane+32 for 8 rows x 2 streams
    float acc1[8][2], acc2[8][2];
    #pragma unroll
    for (int r = 0; r < 8; r++) { acc1[r][0]=0.f; acc1[r][1]=0.f; acc2[r][0]=0.f; acc2[r][1]=0.f; }

    const float* k1b = k1 + bh*SS*HD;
    const float* k2b = k2 + bh*SS*HD;
    const float* vb  = v + (size_t)b*SS*DD + h*HD;
    int lj = t >> 3, ld = (t & 7) << 3;
    int row0 = base + w*8;
    int ntiles = base/32 + 2;

    for (int tt = 0; tt < ntiles; tt++) {
        int kbase = tt * TK;
        __syncthreads();
        {   // stage K tiles (transposed) + V tile
            const float4* p1 = (const float4*)(k1b + (size_t)(kbase + lj)*HD + ld);
            float4 x0 = p1[0], x1 = p1[1];
            k1T[(ld+0)*33+lj]=x0.x; k1T[(ld+1)*33+lj]=x0.y; k1T[(ld+2)*33+lj]=x0.z; k1T[(ld+3)*33+lj]=x0.w;
            k1T[(ld+4)*33+lj]=x1.x; k1T[(ld+5)*33+lj]=x1.y; k1T[(ld+6)*33+lj]=x1.z; k1T[(ld+7)*33+lj]=x1.w;
            const float4* p2 = (const float4*)(k2b + (size_t)(kbase + lj)*HD + ld);
            float4 y0 = p2[0], y1 = p2[1];
            k2T[(ld+0)*33+lj]=y0.x; k2T[(ld+1)*33+lj]=y0.y; k2T[(ld+2)*33+lj]=y0.z; k2T[(ld+3)*33+lj]=y0.w;
            k2T[(ld+4)*33+lj]=y1.x; k2T[(ld+5)*33+lj]=y1.y; k2T[(ld+6)*33+lj]=y1.z; k2T[(ld+7)*33+lj]=y1.w;
            const float4* pv = (const float4*)(vb + (size_t)(kbase + lj)*DD + ld);
            *(float4*)(vs + lj*64 + ld)     = pv[0];
            *(float4*)(vs + lj*64 + ld + 4) = pv[1];
        }
        __syncthreads();

        // QK: lane = key j; 8 rows x 2 streams of dots
        float s1[8], s2[8];
        #pragma unroll
        for (int r = 0; r < 8; r++) { s1[r]=0.f; s2[r]=0.f; }
        for (int dg = 0; dg < 64; dg += 4) {
            float ka0 = k1T[(dg+0)*33+lane], ka1 = k1T[(dg+1)*33+lane];
            float ka2 = k1T[(dg+2)*33+lane], ka3 = k1T[(dg+3)*33+lane];
            float kb0 = k2T[(dg+0)*33+lane], kb1 = k2T[(dg+1)*33+lane];
            float kb2 = k2T[(dg+2)*33+lane], kb3 = k2T[(dg+3)*33+lane];
            #pragma unroll
            for (int r = 0; r < 8; r++) {
                float4 qa = *(const float4*)(q1s + (w*8+r)*64 + dg);
                s1[r] += qa.x*ka0 + qa.y*ka1 + qa.z*ka2 + qa.w*ka3;
                float4 qb = *(const float4*)(q2s + (w*8+r)*64 + dg);
                s2[r] += qb.x*kb0 + qb.y*kb1 + qb.z*kb2 + qb.w*kb3;
            }
        }
        // mask + write raw scores
        #pragma unroll
        for (int r = 0; r < 8; r++) {
            int nv = row0 + r - kbase + 1;
            float u1 = (lane < nv) ? s1[r]*SCALE : -FLT_MAX;
            float u2 = (lane < nv) ? s2[r]*SCALE : -FLT_MAX;
            ps1[(w*8+r)*36 + lane] = u1;
            ps2[(w*8+r)*36 + lane] = u2;
        }
        __syncwarp();

        // online softmax: lane<16, one (row,stream) each; exp in place
        if (lane < 16) {
            float* rowp = (pstr ? ps2 : ps1) + (w*8+pr)*36;
            float4 a0 = *(float4*)(rowp+0),  a1 = *(float4*)(rowp+4);
            float4 a2 = *(float4*)(rowp+8),  a3 = *(float4*)(rowp+12);
            float4 a4 = *(float4*)(rowp+16), a5 = *(float4*)(rowp+20);
            float4 a6 = *(float4*)(rowp+24), a7 = *(float4*)(rowp+28);
            float tm = fmaxf(fmaxf(fmaxf(a0.x,a0.y),fmaxf(a0.z,a0.w)),
                             fmaxf(fmaxf(a1.x,a1.y),fmaxf(a1.z,a1.w)));
            tm = fmaxf(tm, fmaxf(fmaxf(fmaxf(a2.x,a2.y),fmaxf(a2.z,a2.w)),
                                 fmaxf(fmaxf(a3.x,a3.y),fmaxf(a3.z,a3.w))));
            tm = fmaxf(tm, fmaxf(fmaxf(fmaxf(a4.x,a4.y),fmaxf(a4.z,a4.w)),
                                 fmaxf(fmaxf(a5.x,a5.y),fmaxf(a5.z,a5.w))));
            tm = fmaxf(tm, fmaxf(fmaxf(fmaxf(a6.x,a6.y),fmaxf(a6.z,a6.w)),
                                 fmaxf(fmaxf(a7.x,a7.y),fmaxf(a7.z,a7.w))));
            float nm = fmaxf(mst, tm);
            float c = __expf(mst - nm);
            mst = nm;
            float zl = 0.f;
            a0.x=__expf(a0.x-nm); a0.y=__expf(a0.y-nm); a0.z=__expf(a0.z-nm); a0.w=__expf(a0.w-nm);
            a1.x=__expf(a1.x-nm); a1.y=__expf(a1.y-nm); a1.z=__expf(a1.z-nm); a1.w=__expf(a1.w-nm);
            a2.x=__expf(a2.x-nm); a2.y=__expf(a2.y-nm); a2.z=__expf(a2.z-nm); a2.w=__expf(a2.w-nm);
            a3.x=__expf(a3.x-nm); a3.y=__expf(a3.y-nm); a3.z=__expf(a3.z-nm); a3.w=__expf(a3.w-nm);
            a4.x=__expf(a4.x-nm); a4.y=__expf(a4.y-nm); a4.z=__expf(a4.z-nm); a4.w=__expf(a4.w-nm);
            a5.x=__expf(a5.x-nm); a5.y=__expf(a5.y-nm); a5.z=__expf(a5.z-nm); a5.w=__expf(a5.w-nm);
            a6.x=__expf(a6.x-nm); a6.y=__expf(a6.y-nm); a6.z=__expf(a6.z-nm); a6.w=__expf(a6.w-nm);
            a7.x=__expf(a7.x-nm); a7.y=__expf(a7.y-nm); a7.z=__expf(a7.z-nm); a7.w=__expf(a7.w-nm);
            zl = (a0.x+a0.y+a0.z+a0.w) + (a1.x+a1.y+a1.z+a1.w)
               + (a2.x+a2.y+a2.z+a2.w) + (a3.x+a3.y+a3.z+a3.w)
               + (a4.x+a4.y+a4.z+a4.w) + (a5.x+a5.y+a5.z+a5.w)
               + (a6.x+a6.y+a6.z+a6.w) + (a7.x+a7.y+a7.z+a7.w);
            zst = zst*c + zl;
            *(float4*)(rowp+0)=a0;  *(float4*)(rowp+4)=a1;
            *(float4*)(rowp+8)=a2;  *(float4*)(rowp+12)=a3;
            *(float4*)(rowp+16)=a4; *(float4*)(rowp+20)=a5;
            *(float4*)(rowp+24)=a6; *(float4*)(rowp+28)=a7;
            cs[(w*8+pr)*2 + pstr] = c;
        }
        __syncwarp();

        // PV: rescale accumulators, then A*V
        #pragma unroll
        for (int r = 0; r < 8; r++) {
            float c1 = cs[(w*8+r)*2+0], c2 = cs[(w*8+r)*2+1];
            acc1[r][0]*=c1; acc1[r][1]*=c1;
            acc2[r][0]*=c2; acc2[r][1]*=c2;
        }
        for (int jg = 0; jg < 32; jg += 4) {
            float va0 = vs[(jg+0)*64+lane],    va1 = vs[(jg+1)*64+lane];
            float va2 = vs[(jg+2)*64+lane],    va3 = vs[(jg+3)*64+lane];
            float vb0 = vs[(jg+0)*64+lane+32], vb1 = vs[(jg+1)*64+lane+32];
            float vb2 = vs[(jg+2)*64+lane+32], vb3 = vs[(jg+3)*64+lane+32];
            #pragma unroll
            for (int r = 0; r < 8; r++) {
                float4 p1f = *(const float4*)(ps1 + (w*8+r)*36 + jg);
                acc1[r][0] += p1f.x*va0 + p1f.y*va1 + p1f.z*va2 + p1f.w*va3;
                acc1[r][1] += p1f.x*vb0 + p1f.y*vb1 + p1f.z*vb2 + p1f.w*vb3;
                float4 p2f = *(const float4*)(ps2 + (w*8+r)*36 + jg);
                acc2[r][0] += p2f.x*va0 + p2f.y*va1 + p2f.z*va2 + p2f.w*va3;
                acc2[r][1] += p2f.x*vb0 + p2f.y*vb1 + p2f.z*vb2 + p2f.w*vb3;
            }
        }
    }

    // publish z (reuse cs), then epilogue
    if (lane < 16) cs[(w*8+pr)*2 + pstr] = zst;
    __syncwarp();
    float lam = g_lam[h];
    float hw0 = hw[h*HD + lane], hw1 = hw[h*HD + lane + 32];
    #pragma unroll
    for (int r = 0; r < 8; r++) {
        float z1 = cs[(w*8+r)*2+0], z2 = cs[(w*8+r)*2+1];
        float o0 = acc1[r][0]/z1 - lam*(acc2[r][0]/z2);
        float o1 = acc1[r][1]/z1 - lam*(acc2[r][1]/z2);
        float ssum = o0*o0 + o1*o1;
        #pragma unroll
        for (int o = 16; o > 0; o >>= 1)
            ssum += __shfl_xor_sync(0xffffffffu, ssum, o);
        float rs = rsqrtf(ssum * (1.f/64.f) + 1e-6f);
        float sc = 0.8f * rs;
        size_t oo = ((size_t)(b*SS + row0 + r)) * DD + h*HD;
        out[oo + lane]      = o0 * sc * hw0;
        out[oo + lane + 32] = o1 * sc * hw1;
    }
}

// ---------------------------------------------------------------------------
extern "C" void kernel_launch(void* const* d_in, const int* in_sizes, int n_in,
                              void* d_out, int out_size) {
    const float* x   = (const float*)d_in[0];
    const float* Wq  = (const float*)d_in[1];
    const float* bq  = (const float*)d_in[2];
    const float* Wk  = (const float*)d_in[3];
    const float* bk  = (const float*)d_in[4];
    const float* Wv  = (const float*)d_in[5];
    const float* bv  = (const float*)d_in[6];
    const float* Wo  = (const float*)d_in[7];
    const float* bo  = (const float*)d_in[8];
    const float* hw  = (const float*)d_in[9];
    const float* lq1 = (const float*)d_in[10];
    const float* lk1 = (const float*)d_in[11];
    const float* lq2 = (const float*)d_in[12];
    const float* lk2 = (const float*)d_in[13];

    float *qbuf, *kbuf, *vbuf, *q1, *q2, *k1, *k2, *o2;
    cudaGetSymbolAddress((void**)&qbuf, g_qbuf);
    cudaGetSymbolAddress((void**)&kbuf, g_kbuf);
    cudaGetSymbolAddress((void**)&vbuf, g_vbuf);
    cudaGetSymbolAddress((void**)&q1,   g_q1);
    cudaGetSymbolAddress((void**)&q2,   g_q2);
    cudaGetSymbolAddress((void**)&k1,   g_k1);
    cudaGetSymbolAddress((void**)&k2,   g_k2);
    cudaGetSymbolAddress((void**)&o2,   g_o2);

    cudaFuncSetAttribute(attn_kernel, cudaFuncAttributeMaxDynamicSharedMemorySize,
                         ATTN_SMEM_BYTES);

    lambda_kernel<<<1, 32>>>(lq1, lk1, lq2, lk2);
    gemm_qkv<<<dim3(40, 32), 256>>>(x, Wq, bq, Wk, bk, Wv, bv, qbuf, kbuf, vbuf);
    int nrope = BB*HH*SS*HD;
    rope_kernel<<<nrope/256, 256>>>(qbuf, q1, q2);
    rope_kernel<<<nrope/256, 256>>>(kbuf, k1, k2);
    attn_kernel<<<dim3(SS/64, HH, BB), 256, ATTN_SMEM_BYTES>>>(q1, q2, k1, k2, vbuf, hw, o2);
    gemm_nt_bias<<<dim3(8, 32), 256>>>(o2, Wo, bo, (float*)d_out, BB*SS, DD, DD);
}